// round 15
// baseline (speedup 1.0000x reference)
#include <cuda_runtime.h>
#include <mma.h>
#include <cstdint>

using namespace nvcuda;

#define NTOK    16384
#define DMODEL  1024
#define HIDDEN_ 4096

#define BM 128
#define BN 128
#define BK 64
#define SA 68                    // A smem stride (floats), mult of 4
#define SB 132                   // B smem stride (floats), mult of 4
#define ASZ (BM*SA)              // 8704 floats
#define BSZ (BK*SB)              // 8448 floats
#define STG (ASZ+BSZ)            // 17152 floats per stage
#define SMEM_BYTES (2*STG*4)     // 137216 bytes

// ------------------------- device scratch (no runtime alloc) -------------------------
__device__ float g_H[(size_t)(2*NTOK + 256) * HIDDEN_];  // shared hidden [0,N) + routed padded [N, ...)
__device__ int   g_gather[NTOK + 256];
__device__ int   g_eid[NTOK];
__device__ int   g_slot[NTOK];
__device__ int   g_cnt[2];
__device__ int   g_meta[4];          // base0, base1, pc0, pc1
__device__ float g_part[16 * DMODEL];
__device__ float g_addvec[2 * DMODEL];   // add_vec[e] = b2[e] + relu(b1[1-e])@w2[1-e] + b2[1-e]

// ------------------------- small helpers -------------------------
__device__ __forceinline__ void cp16(uint32_t dst, const void* src, unsigned sz) {
    asm volatile("cp.async.cg.shared.global [%0], [%1], 16, %2;\n" :: "r"(dst), "l"(src), "r"(sz));
}

// ------------------------- GEMM core (tf32 wmma, cp.async double buffered) -------------------------
__device__ __forceinline__ void gemm_main(
    float* smem,
    const float* const aptr[8], const unsigned apred[8],
    const float* __restrict__ bptr, int ldb, int ktiles,
    wmma::fragment<wmma::accumulator,16,16,8,float> (&acc)[4][2])
{
    const int tid = threadIdx.x;
    const uint32_t sbase = (uint32_t)__cvta_generic_to_shared(smem);
    const int ca = (tid & 15) * 4;   // A col (floats) within k-tile
    const int cb = (tid & 31) * 4;   // B col (floats) within n-tile
    const int rb = tid >> 5;
    const int ra = tid >> 4;
    const int wid = tid >> 5, wm = wid >> 2, wn = wid & 3;

    auto load_tile = [&](int s, int kt) {
        uint32_t sA = sbase + (uint32_t)(s * STG) * 4u;
        uint32_t sB = sA + (uint32_t)ASZ * 4u;
#pragma unroll
        for (int i = 0; i < 8; i++) {
            int r = ra + 16 * i;
            cp16(sA + (uint32_t)(r * SA + ca) * 4u, aptr[i] + (size_t)kt * BK + ca, apred[i]);
        }
#pragma unroll
        for (int i = 0; i < 8; i++) {
            int r = rb + 8 * i;
            cp16(sB + (uint32_t)(r * SB + cb) * 4u, bptr + (size_t)(kt * BK + r) * ldb + cb, 16u);
        }
        asm volatile("cp.async.commit_group;\n");
    };

    load_tile(0, 0);
    for (int kt = 0; kt < ktiles; kt++) {
        if (kt + 1 < ktiles) {
            load_tile((kt + 1) & 1, kt + 1);
            asm volatile("cp.async.wait_group 1;\n");
        } else {
            asm volatile("cp.async.wait_group 0;\n");
        }
        __syncthreads();
        const float* As = smem + (kt & 1) * STG;
        const float* Bs = As + ASZ;
#pragma unroll
        for (int ks = 0; ks < BK / 8; ks++) {
            wmma::fragment<wmma::matrix_a,16,16,8,wmma::precision::tf32,wmma::row_major> af[4];
            wmma::fragment<wmma::matrix_b,16,16,8,wmma::precision::tf32,wmma::row_major> bf[2];
#pragma unroll
            for (int mi = 0; mi < 4; mi++) {
                wmma::load_matrix_sync(af[mi], As + (wm*64 + mi*16) * SA + ks*8, SA);
#pragma unroll
                for (int t = 0; t < af[mi].num_elements; t++)
                    af[mi].x[t] = wmma::__float_to_tf32(af[mi].x[t]);
            }
#pragma unroll
            for (int ni = 0; ni < 2; ni++) {
                wmma::load_matrix_sync(bf[ni], Bs + (ks*8) * SB + wn*32 + ni*16, SB);
#pragma unroll
                for (int t = 0; t < bf[ni].num_elements; t++)
                    bf[ni].x[t] = wmma::__float_to_tf32(bf[ni].x[t]);
            }
#pragma unroll
            for (int mi = 0; mi < 4; mi++)
#pragma unroll
                for (int ni = 0; ni < 2; ni++)
                    wmma::mma_sync(acc[mi][ni], af[mi], bf[ni], acc[mi][ni]);
        }
        __syncthreads();
    }
}

__device__ __forceinline__ void stage_acc(
    float* smem, wmma::fragment<wmma::accumulator,16,16,8,float> (&acc)[4][2])
{
    int wid = threadIdx.x >> 5, wm = wid >> 2, wn = wid & 3;
#pragma unroll
    for (int mi = 0; mi < 4; mi++)
#pragma unroll
        for (int ni = 0; ni < 2; ni++)
            wmma::store_matrix_sync(smem + (size_t)(wm*64 + mi*16) * SB + wn*32 + ni*16,
                                    acc[mi][ni], SB, wmma::mem_row_major);
    __syncthreads();
}

// ------------------------- small kernels -------------------------
__global__ void k_init() {
    if (threadIdx.x < 2) g_cnt[threadIdx.x] = 0;
}

__global__ void k_gate(const float* __restrict__ x, const float* __restrict__ gw) {
    __shared__ float sg[2 * DMODEL];
    int tid = threadIdx.x;
    for (int i = tid; i < 2 * DMODEL; i += 256) sg[i] = gw[i];
    __syncthreads();
    int warp = tid >> 5, lane = tid & 31;
    int t = blockIdx.x * 8 + warp;
    const float* xr = x + (size_t)t * DMODEL;
    float s0 = 0.f, s1 = 0.f;
    for (int i = lane; i < DMODEL; i += 32) {
        float xv = xr[i];
        s0 += xv * sg[i];
        s1 += xv * sg[DMODEL + i];
    }
#pragma unroll
    for (int o = 16; o; o >>= 1) {
        s0 += __shfl_xor_sync(0xffffffffu, s0, o);
        s1 += __shfl_xor_sync(0xffffffffu, s1, o);
    }
    if (lane == 0) {
        int e = (s1 > s0) ? 1 : 0;     // jnp.argmax tie -> index 0
        g_eid[t] = e;
        g_slot[t] = atomicAdd(&g_cnt[e], 1);
    }
}

__global__ void k_meta() {
    int c0 = g_cnt[0], c1 = g_cnt[1];
    int pc0 = (c0 + 127) & ~127;
    int pc1 = (c1 + 127) & ~127;
    g_meta[0] = 0; g_meta[1] = pc0; g_meta[2] = pc0; g_meta[3] = pc1;
}

__global__ void k_fill() {
    int i = blockIdx.x * 256 + threadIdx.x;
    if (i < NTOK + 256) g_gather[i] = -1;
}

__global__ void k_scatter() {
    int n = blockIdx.x * 256 + threadIdx.x;
    if (n < NTOK) {
        int e = g_eid[n];
        g_gather[g_meta[e] + g_slot[n]] = n;
    }
}

__global__ void k_addvec_part(const float* __restrict__ b1, const float* __restrict__ w2) {
    int o = blockIdx.x >> 2;
    int d = (blockIdx.x & 3) * 256 + threadIdx.x;
    int hc = blockIdx.y;
    const float* w2o = w2 + (size_t)o * HIDDEN_ * DMODEL;
    const float* b1o = b1 + o * HIDDEN_;
    float s = 0.f;
    int h0 = hc * 512;
#pragma unroll 8
    for (int h = h0; h < h0 + 512; h++)
        s += fmaxf(b1o[h], 0.f) * w2o[(size_t)h * DMODEL + d];
    g_part[(hc * 2 + o) * DMODEL + d] = s;
}

__global__ void k_addvec_red(const float* __restrict__ b2) {
    int i = blockIdx.x * 256 + threadIdx.x;   // 0..2047
    int e = i >> 10, d = i & (DMODEL - 1);
    int o = 1 - e;
    float s = b2[e * DMODEL + d] + b2[o * DMODEL + d];
#pragma unroll
    for (int hc = 0; hc < 8; hc++) s += g_part[(hc * 2 + o) * DMODEL + d];
    g_addvec[i] = s;
}

// ------------------------- GEMM1: hidden = relu(X @ W1 + b1) -------------------------
// grid.y: [0,128) shared path; [128,256) expert0 group; [256,384) expert1 group
__global__ void __launch_bounds__(256)
k_gemm1(const float* __restrict__ x, const float* __restrict__ w1,
        const float* __restrict__ b1, const float* __restrict__ sw1,
        const float* __restrict__ sb1)
{
    extern __shared__ float smem[];
    const int tid = threadIdx.x;
    const int n0 = blockIdx.x * BN;
    const int by = blockIdx.y;

    const float* Bw; const float* bias; const int* gather = nullptr;
    size_t hrow0; int m0;
    if (by < 128) {
        m0 = by * BM; Bw = sw1; bias = sb1; hrow0 = (size_t)m0;
    } else {
        int e  = (by - 128) >> 7;
        int mt = (by - 128) & 127;
        int pc = g_meta[2 + e];
        if (mt * BM >= pc) return;
        int base = g_meta[e];
        m0 = mt * BM;
        gather = g_gather + base;
        Bw = w1 + (size_t)e * DMODEL * HIDDEN_;
        bias = b1 + e * HIDDEN_;
        hrow0 = (size_t)(NTOK + base + m0);
    }

    const float* aptr[8]; unsigned apred[8];
    int ra = tid >> 4;
#pragma unroll
    for (int i = 0; i < 8; i++) {
        int r = ra + 16 * i;
        int trow = gather ? gather[m0 + r] : (m0 + r);
        if (trow >= 0) { aptr[i] = x + (size_t)trow * DMODEL; apred[i] = 16u; }
        else           { aptr[i] = x;                         apred[i] = 0u;  }
    }

    wmma::fragment<wmma::accumulator,16,16,8,float> acc[4][2];
#pragma unroll
    for (int mi = 0; mi < 4; mi++)
#pragma unroll
        for (int ni = 0; ni < 2; ni++)
            wmma::fill_fragment(acc[mi][ni], 0.0f);

    gemm_main(smem, aptr, apred, Bw + n0, HIDDEN_, DMODEL / BK, acc);
    stage_acc(smem, acc);

#pragma unroll
    for (int j = 0; j < 64; j++) {
        int idx = tid + j * 256;
        int r = idx >> 7, c = idx & 127;
        float v = smem[r * SB + c] + bias[n0 + c];
        v = fmaxf(v, 0.f);
        g_H[(hrow0 + r) * HIDDEN_ + (size_t)(n0 + c)] = v;
    }
}

// ------------------------- GEMM2 shared: out = Hs @ sw2 + sb2 -------------------------
__global__ void __launch_bounds__(256)
k_gemm2s(const float* __restrict__ sw2, const float* __restrict__ sb2, float* __restrict__ out)
{
    extern __shared__ float smem[];
    const int tid = threadIdx.x;
    const int n0 = blockIdx.x * BN;
    const int m0 = blockIdx.y * BM;

    const float* aptr[8]; unsigned apred[8];
    int ra = tid >> 4;
#pragma unroll
    for (int i = 0; i < 8; i++) {
        aptr[i] = g_H + (size_t)(m0 + ra + 16 * i) * HIDDEN_;
        apred[i] = 16u;
    }

    wmma::fragment<wmma::accumulator,16,16,8,float> acc[4][2];
#pragma unroll
    for (int mi = 0; mi < 4; mi++)
#pragma unroll
        for (int ni = 0; ni < 2; ni++)
            wmma::fill_fragment(acc[mi][ni], 0.0f);

    gemm_main(smem, aptr, apred, sw2 + n0, DMODEL, HIDDEN_ / BK, acc);
    stage_acc(smem, acc);

#pragma unroll
    for (int j = 0; j < 64; j++) {
        int idx = tid + j * 256;
        int r = idx >> 7, c = idx & 127;
        out[(size_t)(m0 + r) * DMODEL + n0 + c] = smem[r * SB + c] + sb2[n0 + c];
    }
}

// ------------------------- GEMM2 routed: out[t] += Hr @ w2_e + add_vec[e] -------------------------
__global__ void __launch_bounds__(256)
k_gemm2r(const float* __restrict__ w2, float* __restrict__ out)
{
    extern __shared__ float smem[];
    const int tid = threadIdx.x;
    const int n0 = blockIdx.x * BN;
    int e  = blockIdx.y >> 7;
    int mt = blockIdx.y & 127;
    int pc = g_meta[2 + e];
    if (mt * BM >= pc) return;
    int base = g_meta[e];
    int m0 = mt * BM;
    size_t hrow0 = (size_t)(NTOK + base + m0);

    const float* aptr[8]; unsigned apred[8];
    int ra = tid >> 4;
#pragma unroll
    for (int i = 0; i < 8; i++) {
        aptr[i] = g_H + (hrow0 + (size_t)(ra + 16 * i)) * HIDDEN_;
        apred[i] = 16u;
    }

    wmma::fragment<wmma::accumulator,16,16,8,float> acc[4][2];
#pragma unroll
    for (int mi = 0; mi < 4; mi++)
#pragma unroll
        for (int ni = 0; ni < 2; ni++)
            wmma::fill_fragment(acc[mi][ni], 0.0f);

    gemm_main(smem, aptr, apred, w2 + (size_t)e * HIDDEN_ * DMODEL + n0, DMODEL, HIDDEN_ / BK, acc);
    stage_acc(smem, acc);

    const int* gather = g_gather + base;
#pragma unroll
    for (int j = 0; j < 64; j++) {
        int idx = tid + j * 256;
        int r = idx >> 7, c = idx & 127;
        int t = gather[m0 + r];
        if (t >= 0) {
            size_t o = (size_t)t * DMODEL + n0 + c;
            out[o] += smem[r * SB + c] + g_addvec[e * DMODEL + n0 + c];
        }
    }
}

// ------------------------- launch -------------------------
extern "C" void kernel_launch(void* const* d_in, const int* in_sizes, int n_in,
                              void* d_out, int out_size)
{
    const float* x      = (const float*)d_in[0];
    const float* gate_w = (const float*)d_in[1];
    const float* w1     = (const float*)d_in[2];
    const float* b1     = (const float*)d_in[3];
    const float* w2     = (const float*)d_in[4];
    const float* b2     = (const float*)d_in[5];
    const float* sw1    = (const float*)d_in[6];
    const float* sb1    = (const float*)d_in[7];
    const float* sw2    = (const float*)d_in[8];
    const float* sb2    = (const float*)d_in[9];
    float* out = (float*)d_out;

    cudaFuncSetAttribute(k_gemm1,  cudaFuncAttributeMaxDynamicSharedMemorySize, SMEM_BYTES);
    cudaFuncSetAttribute(k_gemm2s, cudaFuncAttributeMaxDynamicSharedMemorySize, SMEM_BYTES);
    cudaFuncSetAttribute(k_gemm2r, cudaFuncAttributeMaxDynamicSharedMemorySize, SMEM_BYTES);

    k_init<<<1, 64>>>();
    k_gate<<<NTOK / 8, 256>>>(x, gate_w);
    k_meta<<<1, 1>>>();
    k_fill<<<(NTOK + 256 + 255) / 256, 256>>>();
    k_scatter<<<NTOK / 256, 256>>>();
    k_addvec_part<<<dim3(8, 8), 256>>>(b1, w2);
    k_addvec_red<<<8, 256>>>(b2);

    k_gemm1<<<dim3(HIDDEN_ / BN, 384), 256, SMEM_BYTES>>>(x, w1, b1, sw1, sb1);
    k_gemm2s<<<dim3(DMODEL / BN, NTOK / BM), 256, SMEM_BYTES>>>(sw2, sb2, out);
    k_gemm2r<<<dim3(DMODEL / BN, 256), 256, SMEM_BYTES>>>(w2, out);
}

// round 16
// speedup vs baseline: 4.6701x; 4.6701x over previous
#include <cuda_runtime.h>
#include <cuda_fp16.h>
#include <mma.h>
#include <cstdint>

using namespace nvcuda;

#define NTOK    16384
#define DMODEL  1024
#define HIDDEN_ 4096

#define BM 128
#define BN 128
#define BK 64
#define STAGES 3
#define SAH 72                     // A smem stride (halves): 64+8
#define SBH 136                    // B smem stride (halves): 128+8
#define ASZH (BM*SAH)              // 9216 halves
#define BSZH (BK*SBH)              // 8704 halves
#define STGH (ASZH+BSZH)           // 17920 halves / stage
#define SBF 132                    // epilogue fp32 staging stride
#define SMEM_BYTES (STAGES*STGH*2 > BM*SBF*4 ? STAGES*STGH*2 : BM*SBF*4)  // 107520

// ------------------------- device scratch (no runtime alloc) -------------------------
__device__ __half g_Hh[(size_t)(2*NTOK + 256) * HIDDEN_];   // fp16 hidden
__device__ __half g_xh[(size_t)NTOK * DMODEL];
__device__ __half g_w1h[(size_t)2 * DMODEL * HIDDEN_];
__device__ __half g_w2h[(size_t)2 * HIDDEN_ * DMODEL];
__device__ __half g_sw1h[(size_t)DMODEL * HIDDEN_];
__device__ __half g_sw2h[(size_t)HIDDEN_ * DMODEL];
__device__ int   g_gather[NTOK + 256];
__device__ int   g_eid[NTOK];
__device__ int   g_slot[NTOK];
__device__ int   g_cnt[2];
__device__ int   g_meta[4];          // base0, base1, pc0, pc1
__device__ float g_part[16 * DMODEL];
__device__ float g_addvec[2 * DMODEL];

// ------------------------- helpers -------------------------
__device__ __forceinline__ void cp16(uint32_t dst, const void* src, unsigned sz) {
    asm volatile("cp.async.cg.shared.global [%0], [%1], 16, %2;\n" :: "r"(dst), "l"(src), "r"(sz));
}

// ------------------------- fp16 GEMM core (m16n16k16, 3-stage cp.async) -------------------------
// A rows gathered via 4 per-thread row pointers; B dense row-major [K, ldb] halves.
__device__ __forceinline__ void gemm_main(
    char* smem_raw,
    const __half* const aptr[4], const unsigned apred[4],
    const __half* __restrict__ bptr, int ldb, int ktiles,
    wmma::fragment<wmma::accumulator,16,16,16,float> (&acc)[4][2])
{
    __half* smem = (__half*)smem_raw;
    const int tid = threadIdx.x;
    const uint32_t sbase = (uint32_t)__cvta_generic_to_shared(smem);
    const int ca = (tid & 7) * 8;    // A col (halves)
    const int cb = (tid & 15) * 8;   // B col (halves)
    const int wid = tid >> 5, wm = wid >> 2, wn = wid & 3;

    auto load_tile = [&](int s, int kt) {
        uint32_t sA = sbase + (uint32_t)(s * STGH) * 2u;
        uint32_t sB = sA + (uint32_t)ASZH * 2u;
        int ra = tid >> 3;           // 0..31
        int rb = tid >> 4;           // 0..15
#pragma unroll
        for (int i = 0; i < 4; i++) {
            int r = ra + 32 * i;
            cp16(sA + (uint32_t)(r * SAH + ca) * 2u, aptr[i] + (size_t)kt * BK + ca, apred[i]);
        }
#pragma unroll
        for (int i = 0; i < 4; i++) {
            int r = rb + 16 * i;
            cp16(sB + (uint32_t)(r * SBH + cb) * 2u, bptr + (size_t)(kt * BK + r) * ldb + cb, 16u);
        }
        asm volatile("cp.async.commit_group;\n");
    };

    load_tile(0, 0);
    if (ktiles > 1) load_tile(1, 1);

    for (int kt = 0; kt < ktiles; kt++) {
        int pf = kt + STAGES - 1;
        if (pf < ktiles) {
            load_tile(pf % STAGES, pf);
            asm volatile("cp.async.wait_group 1;\n");   // STAGES-2
        } else {
            asm volatile("cp.async.wait_group 0;\n");
        }
        __syncthreads();
        const __half* As = smem + (kt % STAGES) * STGH;
        const __half* Bs = As + ASZH;
#pragma unroll
        for (int ks = 0; ks < BK / 16; ks++) {
            wmma::fragment<wmma::matrix_a,16,16,16,__half,wmma::row_major> af[4];
            wmma::fragment<wmma::matrix_b,16,16,16,__half,wmma::row_major> bf[2];
#pragma unroll
            for (int mi = 0; mi < 4; mi++)
                wmma::load_matrix_sync(af[mi], As + (wm*64 + mi*16) * SAH + ks*16, SAH);
#pragma unroll
            for (int ni = 0; ni < 2; ni++)
                wmma::load_matrix_sync(bf[ni], Bs + (ks*16) * SBH + wn*32 + ni*16, SBH);
#pragma unroll
            for (int mi = 0; mi < 4; mi++)
#pragma unroll
                for (int ni = 0; ni < 2; ni++)
                    wmma::mma_sync(acc[mi][ni], af[mi], bf[ni], acc[mi][ni]);
        }
        __syncthreads();
    }
}

__device__ __forceinline__ void stage_acc(
    char* smem_raw, wmma::fragment<wmma::accumulator,16,16,16,float> (&acc)[4][2])
{
    float* smem = (float*)smem_raw;
    int wid = threadIdx.x >> 5, wm = wid >> 2, wn = wid & 3;
#pragma unroll
    for (int mi = 0; mi < 4; mi++)
#pragma unroll
        for (int ni = 0; ni < 2; ni++)
            wmma::store_matrix_sync(smem + (size_t)(wm*64 + mi*16) * SBF + wn*32 + ni*16,
                                    acc[mi][ni], SBF, wmma::mem_row_major);
    __syncthreads();
}

// ------------------------- small kernels -------------------------
__global__ void k_init() {
    if (threadIdx.x < 2) g_cnt[threadIdx.x] = 0;
}

__global__ void k_cvt4(const float4* __restrict__ src, __half2* __restrict__ dst, int n4) {
    int i = blockIdx.x * 256 + threadIdx.x;
    if (i < n4) {
        float4 v = src[i];
        dst[2*i]   = __floats2half2_rn(v.x, v.y);
        dst[2*i+1] = __floats2half2_rn(v.z, v.w);
    }
}

__global__ void k_gate(const float* __restrict__ x, const float* __restrict__ gw) {
    __shared__ float sg[2 * DMODEL];
    int tid = threadIdx.x;
    for (int i = tid; i < 2 * DMODEL; i += 256) sg[i] = gw[i];
    __syncthreads();
    int warp = tid >> 5, lane = tid & 31;
    int t = blockIdx.x * 8 + warp;
    const float* xr = x + (size_t)t * DMODEL;
    float s0 = 0.f, s1 = 0.f;
    for (int i = lane; i < DMODEL; i += 32) {
        float xv = xr[i];
        s0 += xv * sg[i];
        s1 += xv * sg[DMODEL + i];
    }
#pragma unroll
    for (int o = 16; o; o >>= 1) {
        s0 += __shfl_xor_sync(0xffffffffu, s0, o);
        s1 += __shfl_xor_sync(0xffffffffu, s1, o);
    }
    if (lane == 0) {
        int e = (s1 > s0) ? 1 : 0;     // jnp.argmax tie -> index 0
        g_eid[t] = e;
        g_slot[t] = atomicAdd(&g_cnt[e], 1);
    }
}

__global__ void k_meta() {
    int c0 = g_cnt[0], c1 = g_cnt[1];
    int pc0 = (c0 + 127) & ~127;
    int pc1 = (c1 + 127) & ~127;
    g_meta[0] = 0; g_meta[1] = pc0; g_meta[2] = pc0; g_meta[3] = pc1;
}

__global__ void k_fill() {
    int i = blockIdx.x * 256 + threadIdx.x;
    if (i < NTOK + 256) g_gather[i] = -1;
}

__global__ void k_scatter() {
    int n = blockIdx.x * 256 + threadIdx.x;
    if (n < NTOK) {
        int e = g_eid[n];
        g_gather[g_meta[e] + g_slot[n]] = n;
    }
}

__global__ void k_addvec_part(const float* __restrict__ b1, const float* __restrict__ w2) {
    int o = blockIdx.x >> 2;
    int d = (blockIdx.x & 3) * 256 + threadIdx.x;
    int hc = blockIdx.y;
    const float* w2o = w2 + (size_t)o * HIDDEN_ * DMODEL;
    const float* b1o = b1 + o * HIDDEN_;
    float s = 0.f;
    int h0 = hc * 512;
#pragma unroll 8
    for (int h = h0; h < h0 + 512; h++)
        s += fmaxf(b1o[h], 0.f) * w2o[(size_t)h * DMODEL + d];
    g_part[(hc * 2 + o) * DMODEL + d] = s;
}

__global__ void k_addvec_red(const float* __restrict__ b2) {
    int i = blockIdx.x * 256 + threadIdx.x;   // 0..2047
    int e = i >> 10, d = i & (DMODEL - 1);
    int o = 1 - e;
    float s = b2[e * DMODEL + d] + b2[o * DMODEL + d];
#pragma unroll
    for (int hc = 0; hc < 8; hc++) s += g_part[(hc * 2 + o) * DMODEL + d];
    g_addvec[i] = s;
}

// ------------------------- GEMM1: hidden = relu(X @ W1 + b1) -------------------------
// grid.y: [0,128) shared; [128,256) expert0; [256,384) expert1
__global__ void __launch_bounds__(256)
k_gemm1(const float* __restrict__ b1, const float* __restrict__ sb1)
{
    extern __shared__ char smem_raw[];
    const int tid = threadIdx.x;
    const int n0 = blockIdx.x * BN;
    const int by = blockIdx.y;

    const __half* Bw; const float* bias; const int* gather = nullptr;
    size_t hrow0; int m0;
    if (by < 128) {
        m0 = by * BM; Bw = g_sw1h; bias = sb1; hrow0 = (size_t)m0;
    } else {
        int e  = (by - 128) >> 7;
        int mt = (by - 128) & 127;
        int pc = g_meta[2 + e];
        if (mt * BM >= pc) return;
        int base = g_meta[e];
        m0 = mt * BM;
        gather = g_gather + base;
        Bw = g_w1h + (size_t)e * DMODEL * HIDDEN_;
        bias = b1 + e * HIDDEN_;
        hrow0 = (size_t)(NTOK + base + m0);
    }

    const __half* aptr[4]; unsigned apred[4];
    int ra = tid >> 3;
#pragma unroll
    for (int i = 0; i < 4; i++) {
        int r = ra + 32 * i;
        int trow = gather ? gather[m0 + r] : (m0 + r);
        if (trow >= 0) { aptr[i] = g_xh + (size_t)trow * DMODEL; apred[i] = 16u; }
        else           { aptr[i] = g_xh;                         apred[i] = 0u;  }
    }

    wmma::fragment<wmma::accumulator,16,16,16,float> acc[4][2];
#pragma unroll
    for (int mi = 0; mi < 4; mi++)
#pragma unroll
        for (int ni = 0; ni < 2; ni++)
            wmma::fill_fragment(acc[mi][ni], 0.0f);

    gemm_main(smem_raw, aptr, apred, Bw + n0, HIDDEN_, DMODEL / BK, acc);
    stage_acc(smem_raw, acc);

    const float* smem = (const float*)smem_raw;
#pragma unroll
    for (int j = 0; j < 64; j++) {
        int idx = tid + j * 256;
        int r = idx >> 7, c = idx & 127;
        float v = smem[r * SBF + c] + bias[n0 + c];
        v = fmaxf(v, 0.f);
        g_Hh[(hrow0 + r) * HIDDEN_ + (size_t)(n0 + c)] = __float2half_rn(v);
    }
}

// ------------------------- GEMM2 shared: out = Hs @ sw2 + sb2 -------------------------
__global__ void __launch_bounds__(256)
k_gemm2s(const float* __restrict__ sb2, float* __restrict__ out)
{
    extern __shared__ char smem_raw[];
    const int tid = threadIdx.x;
    const int n0 = blockIdx.x * BN;
    const int m0 = blockIdx.y * BM;

    const __half* aptr[4]; unsigned apred[4];
    int ra = tid >> 3;
#pragma unroll
    for (int i = 0; i < 4; i++) {
        aptr[i] = g_Hh + (size_t)(m0 + ra + 32 * i) * HIDDEN_;
        apred[i] = 16u;
    }

    wmma::fragment<wmma::accumulator,16,16,16,float> acc[4][2];
#pragma unroll
    for (int mi = 0; mi < 4; mi++)
#pragma unroll
        for (int ni = 0; ni < 2; ni++)
            wmma::fill_fragment(acc[mi][ni], 0.0f);

    gemm_main(smem_raw, aptr, apred, g_sw2h + n0, DMODEL, HIDDEN_ / BK, acc);
    stage_acc(smem_raw, acc);

    const float* smem = (const float*)smem_raw;
#pragma unroll
    for (int j = 0; j < 64; j++) {
        int idx = tid + j * 256;
        int r = idx >> 7, c = idx & 127;
        out[(size_t)(m0 + r) * DMODEL + n0 + c] = smem[r * SBF + c] + sb2[n0 + c];
    }
}

// ------------------------- GEMM2 routed: out[t] += Hr @ w2_e + add_vec[e] -------------------------
__global__ void __launch_bounds__(256)
k_gemm2r(float* __restrict__ out)
{
    extern __shared__ char smem_raw[];
    const int tid = threadIdx.x;
    const int n0 = blockIdx.x * BN;
    int e  = blockIdx.y >> 7;
    int mt = blockIdx.y & 127;
    int pc = g_meta[2 + e];
    if (mt * BM >= pc) return;
    int base = g_meta[e];
    int m0 = mt * BM;
    size_t hrow0 = (size_t)(NTOK + base + m0);

    const __half* aptr[4]; unsigned apred[4];
    int ra = tid >> 3;
#pragma unroll
    for (int i = 0; i < 4; i++) {
        aptr[i] = g_Hh + (hrow0 + (size_t)(ra + 32 * i)) * HIDDEN_;
        apred[i] = 16u;
    }

    wmma::fragment<wmma::accumulator,16,16,16,float> acc[4][2];
#pragma unroll
    for (int mi = 0; mi < 4; mi++)
#pragma unroll
        for (int ni = 0; ni < 2; ni++)
            wmma::fill_fragment(acc[mi][ni], 0.0f);

    gemm_main(smem_raw, aptr, apred, g_w2h + (size_t)e * HIDDEN_ * DMODEL + n0, DMODEL, HIDDEN_ / BK, acc);
    stage_acc(smem_raw, acc);

    const float* smem = (const float*)smem_raw;
    const int* gather = g_gather + base;
#pragma unroll
    for (int j = 0; j < 64; j++) {
        int idx = tid + j * 256;
        int r = idx >> 7, c = idx & 127;
        int t = gather[m0 + r];
        if (t >= 0) {
            size_t o = (size_t)t * DMODEL + n0 + c;
            out[o] += smem[r * SBF + c] + g_addvec[e * DMODEL + n0 + c];
        }
    }
}

// ------------------------- launch -------------------------
extern "C" void kernel_launch(void* const* d_in, const int* in_sizes, int n_in,
                              void* d_out, int out_size)
{
    const float* x      = (const float*)d_in[0];
    const float* gate_w = (const float*)d_in[1];
    const float* w1     = (const float*)d_in[2];
    const float* b1     = (const float*)d_in[3];
    const float* w2     = (const float*)d_in[4];
    const float* b2     = (const float*)d_in[5];
    const float* sw1    = (const float*)d_in[6];
    const float* sb1    = (const float*)d_in[7];
    const float* sw2    = (const float*)d_in[8];
    const float* sb2    = (const float*)d_in[9];
    float* out = (float*)d_out;

    cudaFuncSetAttribute(k_gemm1,  cudaFuncAttributeMaxDynamicSharedMemorySize, SMEM_BYTES);
    cudaFuncSetAttribute(k_gemm2s, cudaFuncAttributeMaxDynamicSharedMemorySize, SMEM_BYTES);
    cudaFuncSetAttribute(k_gemm2r, cudaFuncAttributeMaxDynamicSharedMemorySize, SMEM_BYTES);

    // resolve device scratch addresses for conversion targets
    __half2* d_xh;  cudaGetSymbolAddress((void**)&d_xh,  g_xh);
    __half2* d_w1h; cudaGetSymbolAddress((void**)&d_w1h, g_w1h);
    __half2* d_w2h; cudaGetSymbolAddress((void**)&d_w2h, g_w2h);
    __half2* d_sw1h; cudaGetSymbolAddress((void**)&d_sw1h, g_sw1h);
    __half2* d_sw2h; cudaGetSymbolAddress((void**)&d_sw2h, g_sw2h);

    k_init<<<1, 64>>>();
    k_gate<<<NTOK / 8, 256>>>(x, gate_w);
    k_meta<<<1, 1>>>();
    k_fill<<<(NTOK + 256 + 255) / 256, 256>>>();
    k_scatter<<<NTOK / 256, 256>>>();
    k_addvec_part<<<dim3(8, 8), 256>>>(b1, w2);
    k_addvec_red<<<8, 256>>>(b2);

    // fp32 -> fp16 conversions
    int n4;
    n4 = NTOK * DMODEL / 4;
    k_cvt4<<<(n4 + 255) / 256, 256>>>((const float4*)x, d_xh, n4);
    n4 = 2 * DMODEL * HIDDEN_ / 4;
    k_cvt4<<<(n4 + 255) / 256, 256>>>((const float4*)w1, d_w1h, n4);
    k_cvt4<<<(n4 + 255) / 256, 256>>>((const float4*)w2, d_w2h, n4);
    n4 = DMODEL * HIDDEN_ / 4;
    k_cvt4<<<(n4 + 255) / 256, 256>>>((const float4*)sw1, d_sw1h, n4);
    k_cvt4<<<(n4 + 255) / 256, 256>>>((const float4*)sw2, d_sw2h, n4);

    k_gemm1<<<dim3(HIDDEN_ / BN, 384), 256, SMEM_BYTES>>>(b1, sb1);
    k_gemm2s<<<dim3(DMODEL / BN, NTOK / BM), 256, SMEM_BYTES>>>(sb2, out);
    k_gemm2r<<<dim3(DMODEL / BN, 256), 256, SMEM_BYTES>>>(out);
}

// round 17
// speedup vs baseline: 4.6780x; 1.0017x over previous
#include <cuda_runtime.h>
#include <cuda_fp16.h>
#include <mma.h>
#include <cstdint>

using namespace nvcuda;

#define NTOK    16384
#define DMODEL  1024
#define HIDDEN_ 4096

#define BM 128
#define BN 128
#define BK 64
#define STAGES 3
#define SAH 72                     // A smem stride (halves): 64+8
#define SBH 136                    // B smem stride (halves): 128+8
#define ASZH (BM*SAH)              // 9216 halves
#define BSZH (BK*SBH)              // 8704 halves
#define STGH (ASZH+BSZH)           // 17920 halves / stage
#define SBF 132                    // epilogue fp32 staging stride
#define SMEM_BYTES (STAGES*STGH*2 > BM*SBF*4 ? STAGES*STGH*2 : BM*SBF*4)  // 107520

// ------------------------- device scratch (no runtime alloc) -------------------------
__device__ __half g_Hh[(size_t)(2*NTOK + 256) * HIDDEN_];   // fp16 hidden
__device__ __half g_xh[(size_t)NTOK * DMODEL];
__device__ __half g_w1h[(size_t)2 * DMODEL * HIDDEN_];
__device__ __half g_w2h[(size_t)2 * HIDDEN_ * DMODEL];
__device__ __half g_sw1h[(size_t)DMODEL * HIDDEN_];
__device__ __half g_sw2h[(size_t)HIDDEN_ * DMODEL];
__device__ int   g_gather[NTOK + 256];
__device__ int   g_eid[NTOK];
__device__ int   g_slot[NTOK];
__device__ int   g_cnt[2];
__device__ int   g_meta[4];          // base0, base1, pc0, pc1
__device__ float g_part[16 * DMODEL];
__device__ float g_addvec[2 * DMODEL];

// ------------------------- helpers -------------------------
__device__ __forceinline__ void cp16(uint32_t dst, const void* src, unsigned sz) {
    asm volatile("cp.async.cg.shared.global [%0], [%1], 16, %2;\n" :: "r"(dst), "l"(src), "r"(sz));
}

// ------------------------- fp16 GEMM core (m16n16k16, 3-stage cp.async) -------------------------
// A rows gathered via 4 per-thread row pointers; B dense row-major [K, ldb] halves.
__device__ __forceinline__ void gemm_main(
    char* smem_raw,
    const __half* const aptr[4], const unsigned apred[4],
    const __half* __restrict__ bptr, int ldb, int ktiles,
    wmma::fragment<wmma::accumulator,16,16,16,float> (&acc)[4][2])
{
    __half* smem = (__half*)smem_raw;
    const int tid = threadIdx.x;
    const uint32_t sbase = (uint32_t)__cvta_generic_to_shared(smem);
    const int ca = (tid & 7) * 8;    // A col (halves)
    const int cb = (tid & 15) * 8;   // B col (halves)
    const int wid = tid >> 5, wm = wid >> 2, wn = wid & 3;

    auto load_tile = [&](int s, int kt) {
        uint32_t sA = sbase + (uint32_t)(s * STGH) * 2u;
        uint32_t sB = sA + (uint32_t)ASZH * 2u;
        int ra = tid >> 3;           // 0..31
        int rb = tid >> 4;           // 0..15
#pragma unroll
        for (int i = 0; i < 4; i++) {
            int r = ra + 32 * i;
            cp16(sA + (uint32_t)(r * SAH + ca) * 2u, aptr[i] + (size_t)kt * BK + ca, apred[i]);
        }
#pragma unroll
        for (int i = 0; i < 4; i++) {
            int r = rb + 16 * i;
            cp16(sB + (uint32_t)(r * SBH + cb) * 2u, bptr + (size_t)(kt * BK + r) * ldb + cb, 16u);
        }
        asm volatile("cp.async.commit_group;\n");
    };

    load_tile(0, 0);
    if (ktiles > 1) load_tile(1, 1);

    for (int kt = 0; kt < ktiles; kt++) {
        int pf = kt + STAGES - 1;
        if (pf < ktiles) {
            load_tile(pf % STAGES, pf);
            asm volatile("cp.async.wait_group 1;\n");   // STAGES-2
        } else {
            asm volatile("cp.async.wait_group 0;\n");
        }
        __syncthreads();
        const __half* As = smem + (kt % STAGES) * STGH;
        const __half* Bs = As + ASZH;
#pragma unroll
        for (int ks = 0; ks < BK / 16; ks++) {
            wmma::fragment<wmma::matrix_a,16,16,16,__half,wmma::row_major> af[4];
            wmma::fragment<wmma::matrix_b,16,16,16,__half,wmma::row_major> bf[2];
#pragma unroll
            for (int mi = 0; mi < 4; mi++)
                wmma::load_matrix_sync(af[mi], As + (wm*64 + mi*16) * SAH + ks*16, SAH);
#pragma unroll
            for (int ni = 0; ni < 2; ni++)
                wmma::load_matrix_sync(bf[ni], Bs + (ks*16) * SBH + wn*32 + ni*16, SBH);
#pragma unroll
            for (int mi = 0; mi < 4; mi++)
#pragma unroll
                for (int ni = 0; ni < 2; ni++)
                    wmma::mma_sync(acc[mi][ni], af[mi], bf[ni], acc[mi][ni]);
        }
        __syncthreads();
    }
}

__device__ __forceinline__ void stage_acc(
    char* smem_raw, wmma::fragment<wmma::accumulator,16,16,16,float> (&acc)[4][2])
{
    float* smem = (float*)smem_raw;
    int wid = threadIdx.x >> 5, wm = wid >> 2, wn = wid & 3;
#pragma unroll
    for (int mi = 0; mi < 4; mi++)
#pragma unroll
        for (int ni = 0; ni < 2; ni++)
            wmma::store_matrix_sync(smem + (size_t)(wm*64 + mi*16) * SBF + wn*32 + ni*16,
                                    acc[mi][ni], SBF, wmma::mem_row_major);
    __syncthreads();
}

// ------------------------- small kernels -------------------------
__global__ void k_init() {
    if (threadIdx.x < 2) g_cnt[threadIdx.x] = 0;
}

__global__ void k_cvt4(const float4* __restrict__ src, __half2* __restrict__ dst, int n4) {
    int i = blockIdx.x * 256 + threadIdx.x;
    if (i < n4) {
        float4 v = src[i];
        dst[2*i]   = __floats2half2_rn(v.x, v.y);
        dst[2*i+1] = __floats2half2_rn(v.z, v.w);
    }
}

__global__ void k_gate(const float* __restrict__ x, const float* __restrict__ gw) {
    __shared__ float sg[2 * DMODEL];
    int tid = threadIdx.x;
    for (int i = tid; i < 2 * DMODEL; i += 256) sg[i] = gw[i];
    __syncthreads();
    int warp = tid >> 5, lane = tid & 31;
    int t = blockIdx.x * 8 + warp;
    const float* xr = x + (size_t)t * DMODEL;
    float s0 = 0.f, s1 = 0.f;
    for (int i = lane; i < DMODEL; i += 32) {
        float xv = xr[i];
        s0 += xv * sg[i];
        s1 += xv * sg[DMODEL + i];
    }
#pragma unroll
    for (int o = 16; o; o >>= 1) {
        s0 += __shfl_xor_sync(0xffffffffu, s0, o);
        s1 += __shfl_xor_sync(0xffffffffu, s1, o);
    }
    if (lane == 0) {
        int e = (s1 > s0) ? 1 : 0;     // jnp.argmax tie -> index 0
        g_eid[t] = e;
        g_slot[t] = atomicAdd(&g_cnt[e], 1);
    }
}

__global__ void k_meta() {
    int c0 = g_cnt[0], c1 = g_cnt[1];
    int pc0 = (c0 + 127) & ~127;
    int pc1 = (c1 + 127) & ~127;
    g_meta[0] = 0; g_meta[1] = pc0; g_meta[2] = pc0; g_meta[3] = pc1;
}

__global__ void k_fill() {
    int i = blockIdx.x * 256 + threadIdx.x;
    if (i < NTOK + 256) g_gather[i] = -1;
}

__global__ void k_scatter() {
    int n = blockIdx.x * 256 + threadIdx.x;
    if (n < NTOK) {
        int e = g_eid[n];
        g_gather[g_meta[e] + g_slot[n]] = n;
    }
}

__global__ void k_addvec_part(const float* __restrict__ b1, const float* __restrict__ w2) {
    int o = blockIdx.x >> 2;
    int d = (blockIdx.x & 3) * 256 + threadIdx.x;
    int hc = blockIdx.y;
    const float* w2o = w2 + (size_t)o * HIDDEN_ * DMODEL;
    const float* b1o = b1 + o * HIDDEN_;
    float s = 0.f;
    int h0 = hc * 512;
#pragma unroll 8
    for (int h = h0; h < h0 + 512; h++)
        s += fmaxf(b1o[h], 0.f) * w2o[(size_t)h * DMODEL + d];
    g_part[(hc * 2 + o) * DMODEL + d] = s;
}

__global__ void k_addvec_red(const float* __restrict__ b2) {
    int i = blockIdx.x * 256 + threadIdx.x;   // 0..2047
    int e = i >> 10, d = i & (DMODEL - 1);
    int o = 1 - e;
    float s = b2[e * DMODEL + d] + b2[o * DMODEL + d];
#pragma unroll
    for (int hc = 0; hc < 8; hc++) s += g_part[(hc * 2 + o) * DMODEL + d];
    g_addvec[i] = s;
}

// ------------------------- GEMM1: hidden = relu(X @ W1 + b1) -------------------------
// grid.y: [0,128) shared; [128,256) expert0; [256,384) expert1
__global__ void __launch_bounds__(256)
k_gemm1(const float* __restrict__ b1, const float* __restrict__ sb1)
{
    extern __shared__ char smem_raw[];
    const int tid = threadIdx.x;
    const int n0 = blockIdx.x * BN;
    const int by = blockIdx.y;

    const __half* Bw; const float* bias; const int* gather = nullptr;
    size_t hrow0; int m0;
    if (by < 128) {
        m0 = by * BM; Bw = g_sw1h; bias = sb1; hrow0 = (size_t)m0;
    } else {
        int e  = (by - 128) >> 7;
        int mt = (by - 128) & 127;
        int pc = g_meta[2 + e];
        if (mt * BM >= pc) return;
        int base = g_meta[e];
        m0 = mt * BM;
        gather = g_gather + base;
        Bw = g_w1h + (size_t)e * DMODEL * HIDDEN_;
        bias = b1 + e * HIDDEN_;
        hrow0 = (size_t)(NTOK + base + m0);
    }

    const __half* aptr[4]; unsigned apred[4];
    int ra = tid >> 3;
#pragma unroll
    for (int i = 0; i < 4; i++) {
        int r = ra + 32 * i;
        int trow = gather ? gather[m0 + r] : (m0 + r);
        if (trow >= 0) { aptr[i] = g_xh + (size_t)trow * DMODEL; apred[i] = 16u; }
        else           { aptr[i] = g_xh;                         apred[i] = 0u;  }
    }

    wmma::fragment<wmma::accumulator,16,16,16,float> acc[4][2];
#pragma unroll
    for (int mi = 0; mi < 4; mi++)
#pragma unroll
        for (int ni = 0; ni < 2; ni++)
            wmma::fill_fragment(acc[mi][ni], 0.0f);

    gemm_main(smem_raw, aptr, apred, Bw + n0, HIDDEN_, DMODEL / BK, acc);
    stage_acc(smem_raw, acc);

    const float* smem = (const float*)smem_raw;
#pragma unroll
    for (int j = 0; j < 64; j++) {
        int idx = tid + j * 256;
        int r = idx >> 7, c = idx & 127;
        float v = smem[r * SBF + c] + bias[n0 + c];
        v = fmaxf(v, 0.f);
        g_Hh[(hrow0 + r) * HIDDEN_ + (size_t)(n0 + c)] = __float2half_rn(v);
    }
}

// ------------------------- GEMM2 shared: out = Hs @ sw2 + sb2 -------------------------
__global__ void __launch_bounds__(256)
k_gemm2s(const float* __restrict__ sb2, float* __restrict__ out)
{
    extern __shared__ char smem_raw[];
    const int tid = threadIdx.x;
    const int n0 = blockIdx.x * BN;
    const int m0 = blockIdx.y * BM;

    const __half* aptr[4]; unsigned apred[4];
    int ra = tid >> 3;
#pragma unroll
    for (int i = 0; i < 4; i++) {
        aptr[i] = g_Hh + (size_t)(m0 + ra + 32 * i) * HIDDEN_;
        apred[i] = 16u;
    }

    wmma::fragment<wmma::accumulator,16,16,16,float> acc[4][2];
#pragma unroll
    for (int mi = 0; mi < 4; mi++)
#pragma unroll
        for (int ni = 0; ni < 2; ni++)
            wmma::fill_fragment(acc[mi][ni], 0.0f);

    gemm_main(smem_raw, aptr, apred, g_sw2h + n0, DMODEL, HIDDEN_ / BK, acc);
    stage_acc(smem_raw, acc);

    const float* smem = (const float*)smem_raw;
#pragma unroll
    for (int j = 0; j < 64; j++) {
        int idx = tid + j * 256;
        int r = idx >> 7, c = idx & 127;
        out[(size_t)(m0 + r) * DMODEL + n0 + c] = smem[r * SBF + c] + sb2[n0 + c];
    }
}

// ------------------------- GEMM2 routed: out[t] += Hr @ w2_e + add_vec[e] -------------------------
__global__ void __launch_bounds__(256)
k_gemm2r(float* __restrict__ out)
{
    extern __shared__ char smem_raw[];
    const int tid = threadIdx.x;
    const int n0 = blockIdx.x * BN;
    int e  = blockIdx.y >> 7;
    int mt = blockIdx.y & 127;
    int pc = g_meta[2 + e];
    if (mt * BM >= pc) return;
    int base = g_meta[e];
    int m0 = mt * BM;
    size_t hrow0 = (size_t)(NTOK + base + m0);

    const __half* aptr[4]; unsigned apred[4];
    int ra = tid >> 3;
#pragma unroll
    for (int i = 0; i < 4; i++) {
        aptr[i] = g_Hh + (hrow0 + (size_t)(ra + 32 * i)) * HIDDEN_;
        apred[i] = 16u;
    }

    wmma::fragment<wmma::accumulator,16,16,16,float> acc[4][2];
#pragma unroll
    for (int mi = 0; mi < 4; mi++)
#pragma unroll
        for (int ni = 0; ni < 2; ni++)
            wmma::fill_fragment(acc[mi][ni], 0.0f);

    gemm_main(smem_raw, aptr, apred, g_w2h + (size_t)e * HIDDEN_ * DMODEL + n0, DMODEL, HIDDEN_ / BK, acc);
    stage_acc(smem_raw, acc);

    const float* smem = (const float*)smem_raw;
    const int* gather = g_gather + base;
#pragma unroll
    for (int j = 0; j < 64; j++) {
        int idx = tid + j * 256;
        int r = idx >> 7, c = idx & 127;
        int t = gather[m0 + r];
        if (t >= 0) {
            size_t o = (size_t)t * DMODEL + n0 + c;
            out[o] += smem[r * SBF + c] + g_addvec[e * DMODEL + n0 + c];
        }
    }
}

// ------------------------- launch -------------------------
extern "C" void kernel_launch(void* const* d_in, const int* in_sizes, int n_in,
                              void* d_out, int out_size)
{
    const float* x      = (const float*)d_in[0];
    const float* gate_w = (const float*)d_in[1];
    const float* w1     = (const float*)d_in[2];
    const float* b1     = (const float*)d_in[3];
    const float* w2     = (const float*)d_in[4];
    const float* b2     = (const float*)d_in[5];
    const float* sw1    = (const float*)d_in[6];
    const float* sb1    = (const float*)d_in[7];
    const float* sw2    = (const float*)d_in[8];
    const float* sb2    = (const float*)d_in[9];
    float* out = (float*)d_out;

    cudaFuncSetAttribute(k_gemm1,  cudaFuncAttributeMaxDynamicSharedMemorySize, SMEM_BYTES);
    cudaFuncSetAttribute(k_gemm2s, cudaFuncAttributeMaxDynamicSharedMemorySize, SMEM_BYTES);
    cudaFuncSetAttribute(k_gemm2r, cudaFuncAttributeMaxDynamicSharedMemorySize, SMEM_BYTES);

    // resolve device scratch addresses for conversion targets
    __half2* d_xh;  cudaGetSymbolAddress((void**)&d_xh,  g_xh);
    __half2* d_w1h; cudaGetSymbolAddress((void**)&d_w1h, g_w1h);
    __half2* d_w2h; cudaGetSymbolAddress((void**)&d_w2h, g_w2h);
    __half2* d_sw1h; cudaGetSymbolAddress((void**)&d_sw1h, g_sw1h);
    __half2* d_sw2h; cudaGetSymbolAddress((void**)&d_sw2h, g_sw2h);

    k_init<<<1, 64>>>();
    k_gate<<<NTOK / 8, 256>>>(x, gate_w);
    k_meta<<<1, 1>>>();
    k_fill<<<(NTOK + 256 + 255) / 256, 256>>>();
    k_scatter<<<NTOK / 256, 256>>>();
    k_addvec_part<<<dim3(8, 8), 256>>>(b1, w2);
    k_addvec_red<<<8, 256>>>(b2);

    // fp32 -> fp16 conversions
    int n4;
    n4 = NTOK * DMODEL / 4;
    k_cvt4<<<(n4 + 255) / 256, 256>>>((const float4*)x, d_xh, n4);
    n4 = 2 * DMODEL * HIDDEN_ / 4;
    k_cvt4<<<(n4 + 255) / 256, 256>>>((const float4*)w1, d_w1h, n4);
    k_cvt4<<<(n4 + 255) / 256, 256>>>((const float4*)w2, d_w2h, n4);
    n4 = DMODEL * HIDDEN_ / 4;
    k_cvt4<<<(n4 + 255) / 256, 256>>>((const float4*)sw1, d_sw1h, n4);
    k_cvt4<<<(n4 + 255) / 256, 256>>>((const float4*)sw2, d_sw2h, n4);

    k_gemm1<<<dim3(HIDDEN_ / BN, 384), 256, SMEM_BYTES>>>(b1, sb1);
    k_gemm2s<<<dim3(DMODEL / BN, NTOK / BM), 256, SMEM_BYTES>>>(sb2, out);
    k_gemm2r<<<dim3(DMODEL / BN, 256), 256, SMEM_BYTES>>>(out);
}